// round 6
// baseline (speedup 1.0000x reference)
#include <cuda_runtime.h>

// Fused: ConvTranspose3d(3->16, k=3, s=2, p=1, out_pad=1) + bias + MaxPool3d(2)
//        + softmax(ch) - subtract, swish, max(ch).
// x: [4,3,64,64,64] f32, w: [3,16,3,3,3], b: [16], subtract: [16] -> out [4,64,64,64]
//
// Lane c=lane&15 owns channel c; half=lane>>4 owns one of 2 adjacent-w voxels.
// R6: odd-w conv candidates kept as f32x2 2-lane dot-product accumulators
// (fma.rn.f32x2, Blackwell-only PTX). {x[wv],x[wv+1]} comes packed for free
// from the tile (loaded as ulonglong2); weight pairs {w2,w0} precomputed.
// 324 scalar FFMA/batch -> 108 FFMA + 108 FFMA2.

#define N_BATCH 4
#define CIN 3
#define COUT 16
#define DIM 64

__device__ __forceinline__ unsigned long long pack2(float lo, float hi) {
    unsigned long long r;
    asm("mov.b64 %0, {%1, %2};" : "=l"(r) : "f"(lo), "f"(hi));
    return r;
}
__device__ __forceinline__ void fma2(unsigned long long& acc,
                                     unsigned long long w,
                                     unsigned long long x) {
    asm("fma.rn.f32x2 %0, %1, %2, %0;" : "+l"(acc) : "l"(w), "l"(x));
}
__device__ __forceinline__ float lo_f(unsigned long long v) {
    float a, b;
    asm("mov.b64 {%0, %1}, %2;" : "=f"(a), "=f"(b) : "l"(v));
    return a;
}
__device__ __forceinline__ float hsum2(unsigned long long v) {
    float a, b;
    asm("mov.b64 {%0, %1}, %2;" : "=f"(a), "=f"(b) : "l"(v));
    return a + b;
}

__global__ __launch_bounds__(128, 4) void fused_ctmp_softswish_kernel(
    const float* __restrict__ x,
    const float* __restrict__ wgt,
    const float* __restrict__ bias_g,
    const float* __restrict__ sub_g,
    float* __restrict__ out)
{
    // tile[warp][comb][p][q] = {x_row[4q+p], +1, +2, +3}; comb = cin*4+dd*2+hh
    __shared__ float4 tile[4][12][2][16];

    const int lane = threadIdx.x & 31;
    const int wid  = threadIdx.x >> 5;
    const int c    = lane & 15;
    const int half = lane >> 4;

    // weights for channel c: 27 scalars (kw=1) + 27 packed pairs {kw=2, kw=0}
    float w1r[27];
    unsigned long long w20r[27];
    #pragma unroll
    for (int cin = 0; cin < CIN; ++cin) {
        #pragma unroll
        for (int kd = 0; kd < 3; ++kd) {
            #pragma unroll
            for (int kh = 0; kh < 3; ++kh) {
                const int gbase = (((cin * COUT + c) * 3 + kd) * 3 + kh) * 3;
                const int i = cin * 9 + kd * 3 + kh;
                const float wv0 = __ldg(&wgt[gbase + 0]);
                const float wv1 = __ldg(&wgt[gbase + 1]);
                const float wv2 = __ldg(&wgt[gbase + 2]);
                w1r[i]  = wv1;
                w20r[i] = pack2(wv2, wv0);   // lo pairs with x[wv], hi with x[wv+1]
            }
        }
    }
    const float bias = __ldg(&bias_g[c]);
    const float subc = __ldg(&sub_g[c]);

    const int gwarp  = blockIdx.x * 4 + wid;
    const int nwarps = gridDim.x * 4;
    const int nrows  = N_BATCH * DIM * DIM;

    const int bp = lane >> 4;
    const int bq = lane & 15;

    for (int row = gwarp; row < nrows; row += nwarps) {
        const int h = row & 63;
        const int d = (row >> 6) & 63;
        const int n = row >> 12;

        // ---- build parity-split float4 tile ----
        #pragma unroll
        for (int comb = 0; comb < 12; ++comb) {
            const int cin = comb >> 2;
            const int dd  = (comb >> 1) & 1;
            const int hh  = comb & 1;
            const int dcur = d + dd;
            const int hcur = h + hh;
            const bool rowok = (dcur < DIM) && (hcur < DIM);
            const float* src = x + (((n * CIN + cin) * DIM + dcur) * DIM + hcur) * DIM;
            const int base = 4 * bq + bp;
            float a0 = 0.f, a1 = 0.f, a2 = 0.f, a3 = 0.f;
            if (rowok) {
                a0 = __ldg(&src[base]);
                a1 = __ldg(&src[base + 1]);
                a2 = __ldg(&src[base + 2]);
                if (base + 3 < DIM) a3 = __ldg(&src[base + 3]);
            }
            tile[wid][comb][bp][bq] = make_float4(a0, a1, a2, a3);
        }
        __syncwarp();

        float* orow = out + ((n * DIM + d) * DIM + h) * DIM;

        for (int w0 = 0; w0 < DIM; w0 += 8) {
            const int q0 = w0 >> 2;
            float m[4];

            #pragma unroll
            for (int jp = 0; jp < 2; ++jp) {
                // acc_e[jj][pd*2+ph]: even-w candidate (scalar)
                // acc_o[jj][pd*2+ph]: odd-w candidate (f32x2 dot-product lanes)
                float acc_e[2][4];
                unsigned long long acc_o[2][4];
                #pragma unroll
                for (int jj = 0; jj < 2; ++jj)
                    #pragma unroll
                    for (int i = 0; i < 4; ++i) { acc_e[jj][i] = 0.f; acc_o[jj][i] = 0ull; }

                #pragma unroll
                for (int comb = 0; comb < 12; ++comb) {
                    const int cin = comb >> 2;
                    const int dd  = (comb >> 1) & 1;
                    const int hh  = comb & 1;
                    const ulonglong2 v = *reinterpret_cast<const ulonglong2*>(
                        &tile[wid][comb][half][q0 + jp]);
                    const unsigned long long xp[2] = {v.x, v.y};  // jj=0, jj=1 pairs

                    // (pd,kd) taps valid for this dd; (ph,kh) for this hh
                    #pragma unroll
                    for (int pd = 0; pd < 2; ++pd) {
                        // dd=0: pd=0 -> kd=1, pd=1 -> kd=2 ; dd=1: only pd=1 -> kd=0
                        if (dd == 1 && pd == 0) continue;
                        const int kd = (dd == 1) ? 0 : (pd == 0 ? 1 : 2);
                        #pragma unroll
                        for (int ph = 0; ph < 2; ++ph) {
                            if (hh == 1 && ph == 0) continue;
                            const int kh = (hh == 1) ? 0 : (ph == 0 ? 1 : 2);
                            const int wi = cin * 9 + kd * 3 + kh;
                            const int ai = pd * 2 + ph;
                            #pragma unroll
                            for (int jj = 0; jj < 2; ++jj) {
                                acc_e[jj][ai] = fmaf(w1r[wi], lo_f(xp[jj]), acc_e[jj][ai]);
                                fma2(acc_o[jj][ai], w20r[wi], xp[jj]);
                            }
                        }
                    }
                }

                #pragma unroll
                for (int jj = 0; jj < 2; ++jj) {
                    float mm = fmaxf(fmaxf(acc_e[jj][0], acc_e[jj][1]),
                                     fmaxf(acc_e[jj][2], acc_e[jj][3]));
                    #pragma unroll
                    for (int i = 0; i < 4; ++i)
                        mm = fmaxf(mm, hsum2(acc_o[jj][i]));
                    m[2 * jp + jj] = mm + bias;
                }
            }

            // ---- epilogue: no softmax max-pass; 2 chains interleaved (ILP=4) ----
            float e[4], sum[4];
            #pragma unroll
            for (int j = 0; j < 4; ++j) { e[j] = __expf(m[j]); sum[j] = e[j]; }
            #pragma unroll
            for (int s = 1; s < 16; s <<= 1) {
                #pragma unroll
                for (int j = 0; j < 4; ++j)
                    sum[j] += __shfl_xor_sync(0xffffffffu, sum[j], s);
            }

            float r[4];
            #pragma unroll
            for (int j = 0; j < 4; ++j) {
                const float sft = __fdividef(e[j], sum[j]);
                const float z   = sft - subc;
                r[j] = __fdividef(z, 1.f + __expf(-z));   // swish
            }
            #pragma unroll
            for (int s = 1; s < 16; s <<= 1) {
                #pragma unroll
                for (int j = 0; j < 4; ++j)
                    r[j] = fmaxf(r[j], __shfl_xor_sync(0xffffffffu, r[j], s));
            }

            if (c == 0) {
                #pragma unroll
                for (int j = 0; j < 4; ++j)
                    orow[w0 + 2 * j + half] = r[j];
            }
        }
        __syncwarp();
    }
}

extern "C" void kernel_launch(void* const* d_in, const int* in_sizes, int n_in,
                              void* d_out, int out_size) {
    const float* x   = (const float*)d_in[0];
    const float* w   = (const float*)d_in[1];
    const float* b   = (const float*)d_in[2];
    const float* sub = (const float*)d_in[3];
    float* out = (float*)d_out;
    (void)in_sizes; (void)n_in; (void)out_size;
    fused_ctmp_softswish_kernel<<<2048, 128>>>(x, w, b, sub, out);
}